// round 15
// baseline (speedup 1.0000x reference)
#include <cuda_runtime.h>
#include <cuda_bf16.h>
#include <cuda_fp16.h>
#include <math.h>

#define NN 50000
#define EE 500000
#define HH 128
#define HEADS 3
#define CC 10
#define GG 64
#define F_IN 128
#define EPS 1e-5f
#define NEG_SLOPE 0.2f

#define A2PC 36                       // chunk pitch (uints): 36 mod 32 == 4 -> conflict-free
#define CHUNK_UINTS ((128 + 64) * A2PC)          // 6912 uints per buffer
#define GEMM_SMEM_P (2 * CHUNK_UINTS * 4)        // 55296 B double-buffered

// ---------------- static device scratch ----------------
__device__ int   g_is64;
__device__ int   g_csr_src[EE];
__device__ int   g_rowptr[NN + 1];
__device__ int   g_indeg[NN];
__device__ int   g_cursor[NN];
__device__ int   g_batch[NN];
__device__ float g_dinv[NN];
__device__ int   g_part[256];

__device__ __half g_hx[NN * HH];    // x in fp16
__device__ __half g_ha[NN * HH];    // GEMM1 out / SAGE agg
__device__ __half g_hb[NN * HH];    // GCN out (feat)
__device__ __half g_hc[NN * HH];    // SAGE out
__device__ float  g_gout[NN * HH];  // GAT out (fp32, pooled)
__device__ __half2 g_h3[(size_t)NN * HEADS * HH / 2];  // also SAGE-Wr scratch early

__device__ float g_asrc[NN * HEADS];
__device__ float g_adst[NN * HEADS];

__device__ float g_bnsum[3 * HH];
__device__ float g_bnsq[3 * HH];

__device__ float g_pool[GG * HH];
__device__ float g_cnt[GG];

// ---------------- small helpers ----------------
__device__ __forceinline__ float4 ld4(const float* p) { return *reinterpret_cast<const float4*>(p); }
__device__ __forceinline__ void st4(float* p, float4 v) { *reinterpret_cast<float4*>(p) = v; }
__device__ __forceinline__ float4 f4add(float4 a, float4 b) { return make_float4(a.x+b.x, a.y+b.y, a.z+b.z, a.w+b.w); }
__device__ __forceinline__ float4 f4scale(float4 a, float s) { return make_float4(a.x*s, a.y*s, a.z*s, a.w*s); }
__device__ __forceinline__ float lrelu(float x) { return x > 0.f ? x : NEG_SLOPE * x; }
__device__ __forceinline__ unsigned h2u(__half2 h) { return *reinterpret_cast<unsigned*>(&h); }
__device__ __forceinline__ float4 ldh4(const __half2* p) {
    float2 a = __half22float2(p[0]);
    float2 b = __half22float2(p[1]);
    return make_float4(a.x, a.y, b.x, b.y);
}
__device__ __forceinline__ void sth4(__half2* p, float4 v) {
    p[0] = __floats2half2_rn(v.x, v.y);
    p[1] = __floats2half2_rn(v.z, v.w);
}

// ---------------- preprocessing ----------------
__global__ void k_init(const void* batch, const void* edge) {
    __shared__ int s_is64;
    if (threadIdx.x < 32) {
        const int* p = (const int*)edge;
        int v = p[2 * threadIdx.x + 1];
        unsigned ball = __ballot_sync(0xffffffffu, v != 0);
        if (threadIdx.x == 0) {
            s_is64 = (ball == 0) ? 1 : 0;
            if (blockIdx.x == 0) g_is64 = s_is64;
        }
    }
    __syncthreads();
    int is64 = s_is64;
    int n = blockIdx.x * blockDim.x + threadIdx.x;
    if (n < GG * HH) g_pool[n] = 0.f;
    if (n < GG) g_cnt[n] = 0.f;
    if (n < 3 * HH) { g_bnsum[n] = 0.f; g_bnsq[n] = 0.f; }
    if (n < 3 * NN) { g_asrc[n] = 0.f; g_adst[n] = 0.f; }
    if (n >= NN) return;
    g_indeg[n] = 0;
    g_cursor[n] = 0;
    int b;
    if (is64) b = (int)((const long long*)batch)[n];
    else      b = ((const int*)batch)[n];
    g_batch[n] = b;
}

__global__ void k_count(const void* edge) {
    int e = blockIdx.x * blockDim.x + threadIdx.x;
    if (e >= EE) return;
    int d;
    if (g_is64) d = ((const int*)edge)[2 * (e + EE)];
    else        d = ((const int*)edge)[e + EE];
    atomicAdd(&g_indeg[d], 1);
}

__global__ void k_scan_part() {
    __shared__ int sh[256];
    int i = blockIdx.x * 256 + threadIdx.x;
    int v = (i < NN) ? g_indeg[i] : 0;
    sh[threadIdx.x] = v;
    __syncthreads();
    for (int o = 128; o; o >>= 1) {
        if (threadIdx.x < o) sh[threadIdx.x] += sh[threadIdx.x + o];
        __syncthreads();
    }
    if (threadIdx.x == 0) g_part[blockIdx.x] = sh[0];
}

__global__ void k_scan_mid(int nblk) {
    __shared__ int sh[256];
    int t = threadIdx.x;
    int v = (t < nblk) ? g_part[t] : 0;
    sh[t] = v;
    __syncthreads();
    for (int o = 1; o < 256; o <<= 1) {
        int u = (t >= o) ? sh[t - o] : 0;
        __syncthreads();
        sh[t] += u;
        __syncthreads();
    }
    if (t < nblk) g_part[t] = sh[t] - v;
    if (t == 255) g_rowptr[NN] = sh[255];
}

__global__ void k_scan_out() {
    __shared__ int sh[256];
    int i = blockIdx.x * 256 + threadIdx.x;
    int v = (i < NN) ? g_indeg[i] : 0;
    sh[threadIdx.x] = v;
    __syncthreads();
    for (int o = 1; o < 256; o <<= 1) {
        int u = (threadIdx.x >= o) ? sh[threadIdx.x - o] : 0;
        __syncthreads();
        sh[threadIdx.x] += u;
        __syncthreads();
    }
    if (i < NN) {
        g_rowptr[i] = g_part[blockIdx.x] + sh[threadIdx.x] - v;
        g_dinv[i] = rsqrtf((float)(v + 1));
    }
}

__global__ void k_fill_csr(const void* edge) {
    int e = blockIdx.x * blockDim.x + threadIdx.x;
    if (e >= EE) return;
    int s, d;
    if (g_is64) {
        s = ((const int*)edge)[2 * e];
        d = ((const int*)edge)[2 * (e + EE)];
    } else {
        s = ((const int*)edge)[e];
        d = ((const int*)edge)[e + EE];
    }
    int pos = atomicAdd(&g_cursor[d], 1);
    g_csr_src[g_rowptr[d] + pos] = s;
}

// ---------------- x -> fp16 ----------------
__global__ void k_x2h(const float* __restrict__ x, __half2* __restrict__ out) {
    int i = blockIdx.x * blockDim.x + threadIdx.x;
    if (i >= NN * HH / 4) return;
    float4 v = ld4(x + (size_t)i * 4);
    sth4(out + (size_t)i * 2, v);
}

// ================= pipelined fp16 tensor-core GEMM =================
// Block tile 128x64, 8 warps (4 row x 2 col), warp tile 32x32, mma m16n8k16.
// K split in 64-half chunks, double-buffered smem; next chunk's LDGs overlap mma.
__device__ __forceinline__ void prefA_h(uint4* pa, const __half* Ap, int row0, int M,
                                        int t, int ch) {
#pragma unroll
    for (int i = 0; i < 4; i++) {
        int idx = t + i * 256;
        int r = idx >> 3, q = idx & 7;         // 128 rows x 8 uint4
        pa[i] = make_uint4(0, 0, 0, 0);
        if (row0 + r < M)
            pa[i] = reinterpret_cast<const uint4*>(Ap + (size_t)(row0 + r) * HH)[ch * 8 + q];
    }
}
__device__ __forceinline__ void stsA_h(unsigned* As, const uint4* pa, int t) {
#pragma unroll
    for (int i = 0; i < 4; i++) {
        int idx = t + i * 256;
        int r = idx >> 3, q = idx & 7;
        *reinterpret_cast<uint4*>(As + r * A2PC + q * 4) = pa[i];
    }
}
__device__ __forceinline__ void prefB(float2* pb, const float* Wp, int P, int col0,
                                      int t, int ch) {
#pragma unroll
    for (int i = 0; i < 8; i++) {
        int idx = t + i * 256;
        int n = idx & 63, kpl = idx >> 6;      // 64 n x 32 kp
        int kp = ch * 32 + kpl;
        pb[i].x = Wp[(size_t)(2 * kp) * P + col0 + n];
        pb[i].y = Wp[(size_t)(2 * kp + 1) * P + col0 + n];
    }
}
__device__ __forceinline__ void stsB(unsigned* Bs, const float2* pb, int t) {
#pragma unroll
    for (int i = 0; i < 8; i++) {
        int idx = t + i * 256;
        int n = idx & 63, kpl = idx >> 6;
        Bs[n * A2PC + kpl] = h2u(__floats2half2_rn(pb[i].x, pb[i].y));
    }
}

__device__ __forceinline__ void mma_chunk(const unsigned* As, const unsigned* Bs,
                                          float c[2][4][4], int wr, int wn, int lane) {
#pragma unroll
    for (int sub = 0; sub < 4; sub++) {
        const int kp = sub * 8 + (lane & 3);
        unsigned a[2][4], b[4][2];
#pragma unroll
        for (int ma = 0; ma < 2; ma++) {
            const int r = wr * 32 + ma * 16 + (lane >> 2);
            a[ma][0] = As[r * A2PC + kp];
            a[ma][1] = As[(r + 8) * A2PC + kp];
            a[ma][2] = As[r * A2PC + kp + 4];
            a[ma][3] = As[(r + 8) * A2PC + kp + 4];
        }
#pragma unroll
        for (int na = 0; na < 4; na++) {
            const int n = wn * 32 + na * 8 + (lane >> 2);
            b[na][0] = Bs[n * A2PC + kp];
            b[na][1] = Bs[n * A2PC + kp + 4];
        }
#pragma unroll
        for (int ma = 0; ma < 2; ma++)
#pragma unroll
            for (int na = 0; na < 4; na++)
                asm volatile(
                    "mma.sync.aligned.m16n8k16.row.col.f32.f16.f16.f32 "
                    "{%0,%1,%2,%3},{%4,%5,%6,%7},{%8,%9},{%0,%1,%2,%3};"
                    : "+f"(c[ma][na][0]), "+f"(c[ma][na][1]),
                      "+f"(c[ma][na][2]), "+f"(c[ma][na][3])
                    : "r"(a[ma][0]), "r"(a[ma][1]), "r"(a[ma][2]), "r"(a[ma][3]),
                      "r"(b[na][0]), "r"(b[na][1]));
    }
}

// GEMM: C = A@W (+bias) (+addC), half2 out, optional BN stats
__global__ __launch_bounds__(256) void k_mma_gemm(
    const __half* __restrict__ A, const float* __restrict__ W,
    const float* __restrict__ bias, const __half2* __restrict__ addC,
    __half2* __restrict__ C, int M, int P, int bn_layer)
{
    extern __shared__ unsigned dsm[];
    const int t = threadIdx.x;
    const int lane = t & 31, warp = t >> 5;
    const int wr = warp & 3, wn = warp >> 2;
    const int row0 = blockIdx.y * 128, col0 = blockIdx.x * 64;

    float c[2][4][4];
#pragma unroll
    for (int i = 0; i < 2; i++)
#pragma unroll
        for (int j = 0; j < 4; j++)
#pragma unroll
            for (int q = 0; q < 4; q++) c[i][j][q] = 0.f;

    uint4 pa[4];
    float2 pb[8];
    prefA_h(pa, A, row0, M, t, 0);
    prefB(pb, W, P, col0, t, 0);

    for (int ch = 0; ch < 2; ch++) {
        unsigned* As = dsm + (ch & 1) * CHUNK_UINTS;
        unsigned* Bs = As + 128 * A2PC;
        stsA_h(As, pa, t);
        stsB(Bs, pb, t);
        __syncthreads();
        if (ch == 0) {
            prefA_h(pa, A, row0, M, t, 1);
            prefB(pb, W, P, col0, t, 1);
        }
        mma_chunk(As, Bs, c, wr, wn, lane);
    }

    float ps[4][2], pq[4][2];
#pragma unroll
    for (int na = 0; na < 4; na++) { ps[na][0] = ps[na][1] = pq[na][0] = pq[na][1] = 0.f; }

#pragma unroll
    for (int ma = 0; ma < 2; ma++) {
        const int rbase = row0 + wr * 32 + ma * 16 + (lane >> 2);
#pragma unroll
        for (int h = 0; h < 2; h++) {
            const int rr = rbase + h * 8;
            if (rr >= M) continue;
#pragma unroll
            for (int na = 0; na < 4; na++) {
                const int cc = col0 + wn * 32 + na * 8 + (lane & 3) * 2;
                float vx = c[ma][na][h * 2 + 0];
                float vy = c[ma][na][h * 2 + 1];
                if (bias) { vx += bias[cc]; vy += bias[cc + 1]; }
                if (addC) {
                    float2 av = __half22float2(addC[(size_t)rr * (P / 2) + (cc >> 1)]);
                    vx += av.x; vy += av.y;
                }
                C[(size_t)rr * (P / 2) + (cc >> 1)] = __floats2half2_rn(vx, vy);
                ps[na][0] += vx; pq[na][0] += vx * vx;
                ps[na][1] += vy; pq[na][1] += vy * vy;
            }
        }
    }

    if (bn_layer >= 0) {
#pragma unroll
        for (int na = 0; na < 4; na++)
#pragma unroll
            for (int cq = 0; cq < 2; cq++) {
                float s = ps[na][cq], q = pq[na][cq];
#pragma unroll
                for (int o = 4; o < 32; o <<= 1) {
                    s += __shfl_xor_sync(0xffffffffu, s, o);
                    q += __shfl_xor_sync(0xffffffffu, q, o);
                }
                if ((lane >> 2) == 0) {
                    int col = col0 + wn * 32 + na * 8 + (lane & 3) * 2 + cq;
                    atomicAdd(&g_bnsum[bn_layer * HH + col], s);
                    atomicAdd(&g_bnsq[bn_layer * HH + col], q);
                }
            }
    }
}

// GAT GEMM: P=384, half2 out + fused attention dots
__global__ __launch_bounds__(256) void k_mma_gemm_gat(
    const __half* __restrict__ A, const float* __restrict__ W,
    const float* __restrict__ att_src, const float* __restrict__ att_dst,
    __half2* __restrict__ C, int M)
{
    const int P = HEADS * HH;
    extern __shared__ unsigned dsm[];
    const int t = threadIdx.x;
    const int lane = t & 31, warp = t >> 5;
    const int wr = warp & 3, wn = warp >> 2;
    const int row0 = blockIdx.y * 128, col0 = blockIdx.x * 64;
    const int head = col0 >> 7;
    const int jbase = col0 & 127;

    float c[2][4][4];
#pragma unroll
    for (int i = 0; i < 2; i++)
#pragma unroll
        for (int j = 0; j < 4; j++)
#pragma unroll
            for (int q = 0; q < 4; q++) c[i][j][q] = 0.f;

    uint4 pa[4];
    float2 pb[8];
    prefA_h(pa, A, row0, M, t, 0);
    prefB(pb, W, P, col0, t, 0);

    for (int ch = 0; ch < 2; ch++) {
        unsigned* As = dsm + (ch & 1) * CHUNK_UINTS;
        unsigned* Bs = As + 128 * A2PC;
        stsA_h(As, pa, t);
        stsB(Bs, pb, t);
        __syncthreads();
        if (ch == 0) {
            prefA_h(pa, A, row0, M, t, 1);
            prefB(pb, W, P, col0, t, 1);
        }
        mma_chunk(As, Bs, c, wr, wn, lane);
    }

    float asv[4][2], adv[4][2];
#pragma unroll
    for (int na = 0; na < 4; na++) {
        int j = jbase + wn * 32 + na * 8 + (lane & 3) * 2;
        asv[na][0] = att_src[head * HH + j];     asv[na][1] = att_src[head * HH + j + 1];
        adv[na][0] = att_dst[head * HH + j];     adv[na][1] = att_dst[head * HH + j + 1];
    }

#pragma unroll
    for (int ma = 0; ma < 2; ma++) {
        const int rbase = row0 + wr * 32 + ma * 16 + (lane >> 2);
#pragma unroll
        for (int h = 0; h < 2; h++) {
            const int rr = rbase + h * 8;
            float s1 = 0.f, s2 = 0.f;
#pragma unroll
            for (int na = 0; na < 4; na++) {
                float vx = c[ma][na][h * 2 + 0];
                float vy = c[ma][na][h * 2 + 1];
                s1 = fmaf(vx, asv[na][0], fmaf(vy, asv[na][1], s1));
                s2 = fmaf(vx, adv[na][0], fmaf(vy, adv[na][1], s2));
                if (rr < M) {
                    const int cc = col0 + wn * 32 + na * 8 + (lane & 3) * 2;
                    C[(size_t)rr * (P / 2) + (cc >> 1)] = __floats2half2_rn(vx, vy);
                }
            }
            s1 += __shfl_xor_sync(0xffffffffu, s1, 1);
            s1 += __shfl_xor_sync(0xffffffffu, s1, 2);
            s2 += __shfl_xor_sync(0xffffffffu, s2, 1);
            s2 += __shfl_xor_sync(0xffffffffu, s2, 2);
            if ((lane & 3) == 0 && rr < M) {
                atomicAdd(&g_asrc[rr * 3 + head], s1);
                atomicAdd(&g_adst[rr * 3 + head], s2);
            }
        }
    }
}

// ---------------- GCN gather: half in, half out (+ BN stats L0) ----------------
__global__ void k_gcn_gather(const __half2* __restrict__ t, const float* __restrict__ b1,
                             __half2* __restrict__ out) {
    __shared__ float sh_sum[HH], sh_sq[HH];
    const int tix = threadIdx.x;
    if (tix < HH) { sh_sum[tix] = 0.f; sh_sq[tix] = 0.f; }
    __syncthreads();
    const int lane = tix & 31;
    const int gwarp = (blockIdx.x * blockDim.x + tix) >> 5;
    const int nwarp = (gridDim.x * blockDim.x) >> 5;
    float4 b4 = ld4(b1 + lane * 4);
    float4 lsum = make_float4(0.f, 0.f, 0.f, 0.f), lsq = lsum;
    for (int n = gwarp; n < NN; n += nwarp) {
        float dn = g_dinv[n];
        float4 acc = f4scale(ldh4(t + (size_t)n * 64 + lane * 2), dn);
        int beg = g_rowptr[n], end = g_rowptr[n + 1];
        for (int idx = beg; idx < end; idx++) {
            int s = g_csr_src[idx];
            float ds = g_dinv[s];
            float4 v = ldh4(t + (size_t)s * 64 + lane * 2);
            acc.x = fmaf(v.x, ds, acc.x); acc.y = fmaf(v.y, ds, acc.y);
            acc.z = fmaf(v.z, ds, acc.z); acc.w = fmaf(v.w, ds, acc.w);
        }
        acc = f4scale(acc, dn);
        acc = f4add(acc, b4);
        sth4(out + (size_t)n * 64 + lane * 2, acc);
        lsum = f4add(lsum, acc);
        lsq.x = fmaf(acc.x, acc.x, lsq.x); lsq.y = fmaf(acc.y, acc.y, lsq.y);
        lsq.z = fmaf(acc.z, acc.z, lsq.z); lsq.w = fmaf(acc.w, acc.w, lsq.w);
    }
    atomicAdd(&sh_sum[lane * 4 + 0], lsum.x); atomicAdd(&sh_sq[lane * 4 + 0], lsq.x);
    atomicAdd(&sh_sum[lane * 4 + 1], lsum.y); atomicAdd(&sh_sq[lane * 4 + 1], lsq.y);
    atomicAdd(&sh_sum[lane * 4 + 2], lsum.z); atomicAdd(&sh_sq[lane * 4 + 2], lsq.z);
    atomicAdd(&sh_sum[lane * 4 + 3], lsum.w); atomicAdd(&sh_sq[lane * 4 + 3], lsq.w);
    __syncthreads();
    if (tix < HH) {
        atomicAdd(&g_bnsum[tix], sh_sum[tix]);
        atomicAdd(&g_bnsq[tix], sh_sq[tix]);
    }
}

// ---------------- SAGE mean gather: half in/out ----------------
__global__ void k_sage_gather(const __half2* __restrict__ h, __half2* __restrict__ out) {
    int wid = (blockIdx.x * blockDim.x + threadIdx.x) >> 5;
    int lane = threadIdx.x & 31;
    if (wid >= NN) return;
    int n = wid;
    float4 acc = make_float4(0.f, 0.f, 0.f, 0.f);
    int beg = g_rowptr[n], end = g_rowptr[n + 1];
    for (int idx = beg; idx < end; idx++) {
        int s = g_csr_src[idx];
        acc = f4add(acc, ldh4(h + (size_t)s * 64 + lane * 2));
    }
    float inv = 1.f / fmaxf((float)(end - beg), 1.f);
    sth4(out + (size_t)n * 64 + lane * 2, f4scale(acc, inv));
}

// ---------------- BN apply + ELU on half buffer ----------------
__global__ void k_bn_apply_elu_h(__half2* __restrict__ h, const float* __restrict__ gamma,
                                 const float* __restrict__ beta, int layer) {
    int i = blockIdx.x * blockDim.x + threadIdx.x;
    if (i >= NN * HH / 4) return;
    int j = (i * 4) & (HH - 1);
    const float invN = 1.f / (float)NN;
    float4 v = ldh4(h + (size_t)i * 2);
    float y[4] = {v.x, v.y, v.z, v.w};
#pragma unroll
    for (int q = 0; q < 4; q++) {
        float mean = g_bnsum[layer * HH + j + q] * invN;
        float var = fmaxf(g_bnsq[layer * HH + j + q] * invN - mean * mean, 0.f);
        float sc = gamma[j + q] * rsqrtf(var + EPS);
        float sh = beta[j + q] - mean * sc;
        float tt = fmaf(y[q], sc, sh);
        y[q] = tt > 0.f ? tt : expm1f(tt);
    }
    sth4(h + (size_t)i * 2, make_float4(y[0], y[1], y[2], y[3]));
}

// ---------------- GAT gather: inline softmax, half reads, fp32 out (+ BN stats L2) ----------------
__global__ void k_gat_gather(const float* __restrict__ b3, float* __restrict__ out) {
    __shared__ float sh_sum[HH], sh_sq[HH];
    const int tix = threadIdx.x;
    if (tix < HH) { sh_sum[tix] = 0.f; sh_sq[tix] = 0.f; }
    __syncthreads();
    const int lane = tix & 31;
    const int gwarp = (blockIdx.x * blockDim.x + tix) >> 5;
    const int nwarp = (gridDim.x * blockDim.x) >> 5;
    float4 b4 = ld4(b3 + lane * 4);
    float4 lsum = make_float4(0.f, 0.f, 0.f, 0.f), lsq = lsum;
    const __half2* h3 = g_h3;
    for (int n = gwarp; n < NN; n += nwarp) {
        float ad0 = g_adst[n * 3 + 0], ad1 = g_adst[n * 3 + 1], ad2 = g_adst[n * 3 + 2];
        float w0 = expf(lrelu(g_asrc[n * 3 + 0] + ad0));
        float w1 = expf(lrelu(g_asrc[n * 3 + 1] + ad1));
        float w2 = expf(lrelu(g_asrc[n * 3 + 2] + ad2));
        float d0 = w0, d1 = w1, d2 = w2;
        const __half2* bp = h3 + (size_t)n * 192 + lane * 2;
        float2 p0 = __half22float2(bp[0]),   p1 = __half22float2(bp[1]);
        float2 q0 = __half22float2(bp[64]),  q1 = __half22float2(bp[65]);
        float2 r0 = __half22float2(bp[128]), r1 = __half22float2(bp[129]);
        float4 acc0 = make_float4(p0.x * w0, p0.y * w0, p1.x * w0, p1.y * w0);
        float4 acc1 = make_float4(q0.x * w1, q0.y * w1, q1.x * w1, q1.y * w1);
        float4 acc2 = make_float4(r0.x * w2, r0.y * w2, r1.x * w2, r1.y * w2);
        int beg = g_rowptr[n], end = g_rowptr[n + 1];
        for (int idx = beg; idx < end; idx++) {
            int s = g_csr_src[idx];
            float e0 = expf(lrelu(g_asrc[s * 3 + 0] + ad0));
            float e1 = expf(lrelu(g_asrc[s * 3 + 1] + ad1));
            float e2 = expf(lrelu(g_asrc[s * 3 + 2] + ad2));
            d0 += e0; d1 += e1; d2 += e2;
            const __half2* sp = h3 + (size_t)s * 192 + lane * 2;
            float2 a0 = __half22float2(sp[0]),   a1 = __half22float2(sp[1]);
            float2 b0 = __half22float2(sp[64]),  b1_ = __half22float2(sp[65]);
            float2 c0 = __half22float2(sp[128]), c1 = __half22float2(sp[129]);
            acc0.x = fmaf(a0.x, e0, acc0.x); acc0.y = fmaf(a0.y, e0, acc0.y);
            acc0.z = fmaf(a1.x, e0, acc0.z); acc0.w = fmaf(a1.y, e0, acc0.w);
            acc1.x = fmaf(b0.x, e1, acc1.x); acc1.y = fmaf(b0.y, e1, acc1.y);
            acc1.z = fmaf(b1_.x, e1, acc1.z); acc1.w = fmaf(b1_.y, e1, acc1.w);
            acc2.x = fmaf(c0.x, e2, acc2.x); acc2.y = fmaf(c0.y, e2, acc2.y);
            acc2.z = fmaf(c1.x, e2, acc2.z); acc2.w = fmaf(c1.y, e2, acc2.w);
        }
        float i0 = 1.f / d0, i1 = 1.f / d1, i2 = 1.f / d2;
        float4 r;
        r.x = (acc0.x * i0 + acc1.x * i1 + acc2.x * i2) * (1.f / 3.f) + b4.x;
        r.y = (acc0.y * i0 + acc1.y * i1 + acc2.y * i2) * (1.f / 3.f) + b4.y;
        r.z = (acc0.z * i0 + acc1.z * i1 + acc2.z * i2) * (1.f / 3.f) + b4.z;
        r.w = (acc0.w * i0 + acc1.w * i1 + acc2.w * i2) * (1.f / 3.f) + b4.w;
        st4(out + (size_t)n * HH + lane * 4, r);
        lsum = f4add(lsum, r);
        lsq.x = fmaf(r.x, r.x, lsq.x); lsq.y = fmaf(r.y, r.y, lsq.y);
        lsq.z = fmaf(r.z, r.z, lsq.z); lsq.w = fmaf(r.w, r.w, lsq.w);
    }
    atomicAdd(&sh_sum[lane * 4 + 0], lsum.x); atomicAdd(&sh_sq[lane * 4 + 0], lsq.x);
    atomicAdd(&sh_sum[lane * 4 + 1], lsum.y); atomicAdd(&sh_sq[lane * 4 + 1], lsq.y);
    atomicAdd(&sh_sum[lane * 4 + 2], lsum.z); atomicAdd(&sh_sq[lane * 4 + 2], lsq.z);
    atomicAdd(&sh_sum[lane * 4 + 3], lsum.w); atomicAdd(&sh_sq[lane * 4 + 3], lsq.w);
    __syncthreads();
    if (tix < HH) {
        atomicAdd(&g_bnsum[2 * HH + tix], sh_sum[tix]);
        atomicAdd(&g_bnsq[2 * HH + tix], sh_sq[tix]);
    }
}

// ---------------- pooling with fused BN apply + ELU (layer 2) ----------------
__global__ void k_pool_bn(const float* __restrict__ h, const float* __restrict__ gamma,
                          const float* __restrict__ beta) {
    int gw = (blockIdx.x * blockDim.x + threadIdx.x) >> 5;
    int lane = threadIdx.x & 31;
    int n0 = gw * 8;
    if (n0 >= NN) return;
    const float invN = 1.f / (float)NN;
    float4 sc, sh;
    {
        int j = lane * 4;
        float m0 = g_bnsum[2 * HH + j + 0] * invN, m1 = g_bnsum[2 * HH + j + 1] * invN;
        float m2 = g_bnsum[2 * HH + j + 2] * invN, m3 = g_bnsum[2 * HH + j + 3] * invN;
        float v0 = fmaxf(g_bnsq[2 * HH + j + 0] * invN - m0 * m0, 0.f);
        float v1 = fmaxf(g_bnsq[2 * HH + j + 1] * invN - m1 * m1, 0.f);
        float v2 = fmaxf(g_bnsq[2 * HH + j + 2] * invN - m2 * m2, 0.f);
        float v3 = fmaxf(g_bnsq[2 * HH + j + 3] * invN - m3 * m3, 0.f);
        sc.x = gamma[j + 0] * rsqrtf(v0 + EPS); sh.x = beta[j + 0] - m0 * sc.x;
        sc.y = gamma[j + 1] * rsqrtf(v1 + EPS); sh.y = beta[j + 1] - m1 * sc.y;
        sc.z = gamma[j + 2] * rsqrtf(v2 + EPS); sh.z = beta[j + 2] - m2 * sc.z;
        sc.w = gamma[j + 3] * rsqrtf(v3 + EPS); sh.w = beta[j + 3] - m3 * sc.w;
    }
    float4 acc = make_float4(0.f, 0.f, 0.f, 0.f);
    int cur = g_batch[n0];
    float cnt = 0.f;
    for (int j = 0; j < 8; j++) {
        int n = n0 + j;
        if (n >= NN) break;
        int b = g_batch[n];
        float4 v = ld4(h + (size_t)n * HH + lane * 4);
        float y0 = fmaf(v.x, sc.x, sh.x), y1 = fmaf(v.y, sc.y, sh.y);
        float y2 = fmaf(v.z, sc.z, sh.z), y3 = fmaf(v.w, sc.w, sh.w);
        y0 = y0 > 0.f ? y0 : expm1f(y0);
        y1 = y1 > 0.f ? y1 : expm1f(y1);
        y2 = y2 > 0.f ? y2 : expm1f(y2);
        y3 = y3 > 0.f ? y3 : expm1f(y3);
        if (b != cur) {
            float* p = g_pool + (size_t)cur * HH + lane * 4;
            atomicAdd(p + 0, acc.x); atomicAdd(p + 1, acc.y);
            atomicAdd(p + 2, acc.z); atomicAdd(p + 3, acc.w);
            if (lane == 0) atomicAdd(&g_cnt[cur], cnt);
            acc = make_float4(0.f, 0.f, 0.f, 0.f);
            cnt = 0.f;
            cur = b;
        }
        acc.x += y0; acc.y += y1; acc.z += y2; acc.w += y3;
        cnt += 1.f;
    }
    float* p = g_pool + (size_t)cur * HH + lane * 4;
    atomicAdd(p + 0, acc.x); atomicAdd(p + 1, acc.y);
    atomicAdd(p + 2, acc.z); atomicAdd(p + 3, acc.w);
    if (lane == 0) atomicAdd(&g_cnt[cur], cnt);
}

// ---------------- final: normalize pool + classifier ----------------
__global__ void k_pool_fin_cls(const float* __restrict__ Wc, const float* __restrict__ bc,
                               float* __restrict__ outp, float* __restrict__ outl) {
    __shared__ float sm[HH];
    int g = blockIdx.x;
    int t = threadIdx.x;
    float c = g_cnt[g];
    float v = g_pool[g * HH + t] / fmaxf(c, 1.f);
    if (outp) outp[g * HH + t] = v;
    sm[t] = v;
    __syncthreads();
    if (t < CC) {
        float s = bc[t];
        for (int k = 0; k < HH; k++) s = fmaf(sm[k], Wc[k * CC + t], s);
        if (outl) outl[g * CC + t] = s;
    }
}

// ---------------- host ----------------
extern "C" void kernel_launch(void* const* d_in, const int* in_sizes, int n_in,
                              void* d_out, int out_size) {
    const float* x        = (const float*)d_in[0];
    const void*  edge     = d_in[1];
    const void*  batch    = d_in[2];
    const float* W1       = (const float*)d_in[3];
    const float* b1       = (const float*)d_in[4];
    const float* gamma1   = (const float*)d_in[5];
    const float* beta1    = (const float*)d_in[6];
    const float* Wl       = (const float*)d_in[7];
    const float* bl       = (const float*)d_in[8];
    const float* Wr       = (const float*)d_in[9];
    const float* gamma2   = (const float*)d_in[10];
    const float* beta2    = (const float*)d_in[11];
    const float* W3       = (const float*)d_in[12];
    const float* att_src  = (const float*)d_in[13];
    const float* att_dst  = (const float*)d_in[14];
    const float* b3       = (const float*)d_in[15];
    const float* gamma3   = (const float*)d_in[16];
    const float* beta3    = (const float*)d_in[17];
    const float* Wc       = (const float*)d_in[18];
    const float* bc       = (const float*)d_in[19];

    float* out = (float*)d_out;
    float* out_pool = nullptr;
    float* out_log = nullptr;
    if (out_size >= GG * HH + GG * CC) { out_pool = out; out_log = out + GG * HH; }
    else if (out_size == GG * CC) { out_log = out; }
    else { out_pool = out; }

    __half *hx, *ha, *hb, *hc;
    __half2* h3;
    float* gout;
    cudaGetSymbolAddress((void**)&hx, g_hx);
    cudaGetSymbolAddress((void**)&ha, g_ha);
    cudaGetSymbolAddress((void**)&hb, g_hb);
    cudaGetSymbolAddress((void**)&hc, g_hc);
    cudaGetSymbolAddress((void**)&h3, g_h3);
    cudaGetSymbolAddress((void**)&gout, g_gout);

    // one-time host-side resources (no device memory)
    static cudaStream_t s2 = nullptr;
    static cudaEvent_t evA = nullptr, evB = nullptr, evC = nullptr, evD = nullptr;
    if (!s2) {
        cudaStreamCreateWithFlags(&s2, cudaStreamNonBlocking);
        cudaEventCreateWithFlags(&evA, cudaEventDisableTiming);
        cudaEventCreateWithFlags(&evB, cudaEventDisableTiming);
        cudaEventCreateWithFlags(&evC, cudaEventDisableTiming);
        cudaEventCreateWithFlags(&evD, cudaEventDisableTiming);
        cudaFuncSetAttribute(k_mma_gemm, cudaFuncAttributeMaxDynamicSharedMemorySize, GEMM_SMEM_P);
        cudaFuncSetAttribute(k_mma_gemm_gat, cudaFuncAttributeMaxDynamicSharedMemorySize, GEMM_SMEM_P);
    }

    const int EB = (EE + 255) / 256;
    const int NB = (NN + 255) / 256;
    const int IB = (3 * NN + 255) / 256;
    const int WB = (NN * 32 + 255) / 256;
    const int SB = 592;
    const int AB = (NN * HH / 4 + 255) / 256;
    const int MB = (NN + 127) / 128;
    const int PB = ((NN + 7) / 8 * 32 + 255) / 256;

    // ---- fork 1: edge preprocessing (s2) ∥ x2h + GEMM1 (main) ----
    cudaEventRecord(evA, 0);
    cudaStreamWaitEvent(s2, evA, 0);
    k_init<<<IB, 256, 0, s2>>>(batch, edge);
    k_count<<<EB, 256, 0, s2>>>(edge);
    k_scan_part<<<NB, 256, 0, s2>>>();
    k_scan_mid<<<1, 256, 0, s2>>>(NB);
    k_scan_out<<<NB, 256, 0, s2>>>();
    k_fill_csr<<<EB, 256, 0, s2>>>(edge);
    cudaEventRecord(evB, s2);

    k_x2h<<<AB, 256>>>(x, (__half2*)hx);
    k_mma_gemm<<<dim3(HH / 64, MB), 256, GEMM_SMEM_P>>>(hx, W1, nullptr, nullptr,
                                                        (__half2*)ha, NN, HH, -1);
    cudaStreamWaitEvent(0, evB, 0);

    // Layer 1: GCN
    k_gcn_gather<<<SB, 256>>>((__half2*)ha, b1, (__half2*)hb);
    k_bn_apply_elu_h<<<AB, 256>>>((__half2*)hb, gamma1, beta1, 0);

    // ---- fork 2: sage_gather (s2) ∥ GEMM(hb@Wr -> scratch=h3) (main) ----
    cudaEventRecord(evC, 0);
    cudaStreamWaitEvent(s2, evC, 0);
    k_sage_gather<<<WB, 256, 0, s2>>>((__half2*)hb, (__half2*)ha);
    cudaEventRecord(evD, s2);

    k_mma_gemm<<<dim3(HH / 64, MB), 256, GEMM_SMEM_P>>>(hb, Wr, nullptr, nullptr,
                                                        h3, NN, HH, -1);
    cudaStreamWaitEvent(0, evD, 0);
    // Wl GEMM: agg@Wl + bl + scratch, BN stats L1
    k_mma_gemm<<<dim3(HH / 64, MB), 256, GEMM_SMEM_P>>>(ha, Wl, bl, h3,
                                                        (__half2*)hc, NN, HH, 1);
    k_bn_apply_elu_h<<<AB, 256>>>((__half2*)hc, gamma2, beta2, 1);

    // Layer 3: GAT
    k_mma_gemm_gat<<<dim3(HEADS * HH / 64, MB), 256, GEMM_SMEM_P>>>(hc, W3, att_src, att_dst, h3, NN);
    k_gat_gather<<<SB, 256>>>(b3, gout);

    // pooling (fused BN apply L2 + ELU) + classifier
    k_pool_bn<<<PB, 256>>>(gout, gamma3, beta3);
    k_pool_fin_cls<<<GG, HH>>>(Wc, bc, out_pool, out_log);
}

// round 16
// speedup vs baseline: 1.0923x; 1.0923x over previous
#include <cuda_runtime.h>
#include <cuda_bf16.h>
#include <cuda_fp16.h>
#include <math.h>

#define NN 50000
#define EE 500000
#define HH 128
#define HEADS 3
#define CC 10
#define GG 64
#define F_IN 128
#define EPS 1e-5f
#define NEG_SLOPE 0.2f

#define A2PC 36                       // chunk pitch (uints): 36 mod 32 == 4 -> conflict-free
#define CHUNK_UINTS ((128 + 64) * A2PC)          // 6912 uints per buffer
#define GEMM_SMEM_P (2 * CHUNK_UINTS * 4)        // 55296 B double-buffered

// ---------------- static device scratch ----------------
__device__ int   g_is64;
__device__ int   g_csr_src[EE];
__device__ int   g_rowptr[NN + 1];
__device__ int   g_indeg[NN];
__device__ int   g_cursor[NN];
__device__ int   g_batch[NN];
__device__ float g_dinv[NN];
__device__ int   g_part[256];

__device__ __half g_hx[NN * HH];    // x in fp16
__device__ __half g_ha[NN * HH];    // GEMM1 out / SAGE agg
__device__ __half g_hb[NN * HH];    // GCN out (feat)
__device__ __half g_hc[NN * HH];    // SAGE out
__device__ float  g_gout[NN * HH];  // GAT out (fp32, pooled)
__device__ __half2 g_h3[(size_t)NN * HEADS * HH / 2];

__device__ float g_asrc[NN * HEADS];
__device__ float g_adst[NN * HEADS];

__device__ float g_bnsum[3 * HH];
__device__ float g_bnsq[3 * HH];

__device__ float g_pool[GG * HH];
__device__ float g_cnt[GG];

// ---------------- small helpers ----------------
__device__ __forceinline__ float4 ld4(const float* p) { return *reinterpret_cast<const float4*>(p); }
__device__ __forceinline__ void st4(float* p, float4 v) { *reinterpret_cast<float4*>(p) = v; }
__device__ __forceinline__ float4 f4add(float4 a, float4 b) { return make_float4(a.x+b.x, a.y+b.y, a.z+b.z, a.w+b.w); }
__device__ __forceinline__ float4 f4scale(float4 a, float s) { return make_float4(a.x*s, a.y*s, a.z*s, a.w*s); }
__device__ __forceinline__ float lrelu(float x) { return x > 0.f ? x : NEG_SLOPE * x; }
__device__ __forceinline__ float elu1(float t) { return t > 0.f ? t : __expf(t) - 1.f; }
__device__ __forceinline__ unsigned h2u(__half2 h) { return *reinterpret_cast<unsigned*>(&h); }
__device__ __forceinline__ float4 ldh4(const __half2* p) {
    float2 a = __half22float2(p[0]);
    float2 b = __half22float2(p[1]);
    return make_float4(a.x, a.y, b.x, b.y);
}
__device__ __forceinline__ void sth4(__half2* p, float4 v) {
    p[0] = __floats2half2_rn(v.x, v.y);
    p[1] = __floats2half2_rn(v.z, v.w);
}

// ---------------- preprocessing ----------------
__global__ void k_init(const void* batch, const void* edge) {
    __shared__ int s_is64;
    if (threadIdx.x < 32) {
        const int* p = (const int*)edge;
        int v = p[2 * threadIdx.x + 1];
        unsigned ball = __ballot_sync(0xffffffffu, v != 0);
        if (threadIdx.x == 0) {
            s_is64 = (ball == 0) ? 1 : 0;
            if (blockIdx.x == 0) g_is64 = s_is64;
        }
    }
    __syncthreads();
    int is64 = s_is64;
    int n = blockIdx.x * blockDim.x + threadIdx.x;
    if (n < GG * HH) g_pool[n] = 0.f;
    if (n < GG) g_cnt[n] = 0.f;
    if (n < 3 * HH) { g_bnsum[n] = 0.f; g_bnsq[n] = 0.f; }
    if (n < 3 * NN) { g_asrc[n] = 0.f; g_adst[n] = 0.f; }
    if (n >= NN) return;
    g_indeg[n] = 0;
    g_cursor[n] = 0;
    int b;
    if (is64) b = (int)((const long long*)batch)[n];
    else      b = ((const int*)batch)[n];
    g_batch[n] = b;
}

__global__ void k_count(const void* edge) {
    int e = blockIdx.x * blockDim.x + threadIdx.x;
    if (e >= EE) return;
    int d;
    if (g_is64) d = ((const int*)edge)[2 * (e + EE)];
    else        d = ((const int*)edge)[e + EE];
    atomicAdd(&g_indeg[d], 1);
}

__global__ void k_scan_part() {
    __shared__ int sh[256];
    int i = blockIdx.x * 256 + threadIdx.x;
    int v = (i < NN) ? g_indeg[i] : 0;
    sh[threadIdx.x] = v;
    __syncthreads();
    for (int o = 128; o; o >>= 1) {
        if (threadIdx.x < o) sh[threadIdx.x] += sh[threadIdx.x + o];
        __syncthreads();
    }
    if (threadIdx.x == 0) g_part[blockIdx.x] = sh[0];
}

__global__ void k_scan_mid(int nblk) {
    __shared__ int sh[256];
    int t = threadIdx.x;
    int v = (t < nblk) ? g_part[t] : 0;
    sh[t] = v;
    __syncthreads();
    for (int o = 1; o < 256; o <<= 1) {
        int u = (t >= o) ? sh[t - o] : 0;
        __syncthreads();
        sh[t] += u;
        __syncthreads();
    }
    if (t < nblk) g_part[t] = sh[t] - v;
    if (t == 255) g_rowptr[NN] = sh[255];
}

__global__ void k_scan_out() {
    __shared__ int sh[256];
    int i = blockIdx.x * 256 + threadIdx.x;
    int v = (i < NN) ? g_indeg[i] : 0;
    sh[threadIdx.x] = v;
    __syncthreads();
    for (int o = 1; o < 256; o <<= 1) {
        int u = (threadIdx.x >= o) ? sh[threadIdx.x - o] : 0;
        __syncthreads();
        sh[threadIdx.x] += u;
        __syncthreads();
    }
    if (i < NN) {
        g_rowptr[i] = g_part[blockIdx.x] + sh[threadIdx.x] - v;
        g_dinv[i] = rsqrtf((float)(v + 1));
    }
}

__global__ void k_fill_csr(const void* edge) {
    int e = blockIdx.x * blockDim.x + threadIdx.x;
    if (e >= EE) return;
    int s, d;
    if (g_is64) {
        s = ((const int*)edge)[2 * e];
        d = ((const int*)edge)[2 * (e + EE)];
    } else {
        s = ((const int*)edge)[e];
        d = ((const int*)edge)[e + EE];
    }
    int pos = atomicAdd(&g_cursor[d], 1);
    g_csr_src[g_rowptr[d] + pos] = s;
}

// ---------------- x -> fp16 ----------------
__global__ void k_x2h(const float* __restrict__ x, __half2* __restrict__ out) {
    int i = blockIdx.x * blockDim.x + threadIdx.x;
    if (i >= NN * HH / 4) return;
    float4 v = ld4(x + (size_t)i * 4);
    sth4(out + (size_t)i * 2, v);
}

// ================= pipelined fp16 tensor-core GEMM =================
__device__ __forceinline__ void prefA_h(uint4* pa, const __half* Ap, int row0, int M,
                                        int t, int ch) {
#pragma unroll
    for (int i = 0; i < 4; i++) {
        int idx = t + i * 256;
        int r = idx >> 3, q = idx & 7;         // 128 rows x 8 uint4
        pa[i] = make_uint4(0, 0, 0, 0);
        if (row0 + r < M)
            pa[i] = reinterpret_cast<const uint4*>(Ap + (size_t)(row0 + r) * HH)[ch * 8 + q];
    }
}
__device__ __forceinline__ void stsA_h(unsigned* As, const uint4* pa, int t) {
#pragma unroll
    for (int i = 0; i < 4; i++) {
        int idx = t + i * 256;
        int r = idx >> 3, q = idx & 7;
        *reinterpret_cast<uint4*>(As + r * A2PC + q * 4) = pa[i];
    }
}
__device__ __forceinline__ void prefB(float2* pb, const float* Wp, int P, int col0,
                                      int t, int ch) {
#pragma unroll
    for (int i = 0; i < 8; i++) {
        int idx = t + i * 256;
        int n = idx & 63, kpl = idx >> 6;      // 64 n x 32 kp
        int kp = ch * 32 + kpl;
        pb[i].x = Wp[(size_t)(2 * kp) * P + col0 + n];
        pb[i].y = Wp[(size_t)(2 * kp + 1) * P + col0 + n];
    }
}
__device__ __forceinline__ void stsB(unsigned* Bs, const float2* pb, int t) {
#pragma unroll
    for (int i = 0; i < 8; i++) {
        int idx = t + i * 256;
        int n = idx & 63, kpl = idx >> 6;
        Bs[n * A2PC + kpl] = h2u(__floats2half2_rn(pb[i].x, pb[i].y));
    }
}

__device__ __forceinline__ void mma_chunk(const unsigned* As, const unsigned* Bs,
                                          float c[2][4][4], int wr, int wn, int lane) {
#pragma unroll
    for (int sub = 0; sub < 4; sub++) {
        const int kp = sub * 8 + (lane & 3);
        unsigned a[2][4], b[4][2];
#pragma unroll
        for (int ma = 0; ma < 2; ma++) {
            const int r = wr * 32 + ma * 16 + (lane >> 2);
            a[ma][0] = As[r * A2PC + kp];
            a[ma][1] = As[(r + 8) * A2PC + kp];
            a[ma][2] = As[r * A2PC + kp + 4];
            a[ma][3] = As[(r + 8) * A2PC + kp + 4];
        }
#pragma unroll
        for (int na = 0; na < 4; na++) {
            const int n = wn * 32 + na * 8 + (lane >> 2);
            b[na][0] = Bs[n * A2PC + kp];
            b[na][1] = Bs[n * A2PC + kp + 4];
        }
#pragma unroll
        for (int ma = 0; ma < 2; ma++)
#pragma unroll
            for (int na = 0; na < 4; na++)
                asm volatile(
                    "mma.sync.aligned.m16n8k16.row.col.f32.f16.f16.f32 "
                    "{%0,%1,%2,%3},{%4,%5,%6,%7},{%8,%9},{%0,%1,%2,%3};"
                    : "+f"(c[ma][na][0]), "+f"(c[ma][na][1]),
                      "+f"(c[ma][na][2]), "+f"(c[ma][na][3])
                    : "r"(a[ma][0]), "r"(a[ma][1]), "r"(a[ma][2]), "r"(a[ma][3]),
                      "r"(b[na][0]), "r"(b[na][1]));
    }
}

// generic GEMM: optional dual A (K=256 logical), optional bias, half2 out, optional BN stats
__global__ __launch_bounds__(256) void k_mma_gemm(
    const __half* __restrict__ A, const float* __restrict__ W,
    const __half* __restrict__ A2, const float* __restrict__ W2,
    const float* __restrict__ bias, __half2* __restrict__ C,
    int M, int P, int bn_layer)
{
    extern __shared__ unsigned dsm[];
    const int t = threadIdx.x;
    const int lane = t & 31, warp = t >> 5;
    const int wr = warp & 3, wn = warp >> 2;
    const int row0 = blockIdx.y * 128, col0 = blockIdx.x * 64;
    const int nch = A2 ? 4 : 2;

    float c[2][4][4];
#pragma unroll
    for (int i = 0; i < 2; i++)
#pragma unroll
        for (int j = 0; j < 4; j++)
#pragma unroll
            for (int q = 0; q < 4; q++) c[i][j][q] = 0.f;

    uint4 pa[4];
    float2 pb[8];
    prefA_h(pa, A, row0, M, t, 0);
    prefB(pb, W, P, col0, t, 0);

    for (int ch = 0; ch < nch; ch++) {
        unsigned* As = dsm + (ch & 1) * CHUNK_UINTS;
        unsigned* Bs = As + 128 * A2PC;
        stsA_h(As, pa, t);
        stsB(Bs, pb, t);
        __syncthreads();
        if (ch + 1 < nch) {
            const __half* Ap = (ch + 1 < 2) ? A : A2;
            const float* Wp = (ch + 1 < 2) ? W : W2;
            prefA_h(pa, Ap, row0, M, t, (ch + 1) & 1);
            prefB(pb, Wp, P, col0, t, (ch + 1) & 1);
        }
        mma_chunk(As, Bs, c, wr, wn, lane);
    }

    float ps[4][2], pq[4][2];
#pragma unroll
    for (int na = 0; na < 4; na++) { ps[na][0] = ps[na][1] = pq[na][0] = pq[na][1] = 0.f; }

#pragma unroll
    for (int ma = 0; ma < 2; ma++) {
        const int rbase = row0 + wr * 32 + ma * 16 + (lane >> 2);
#pragma unroll
        for (int h = 0; h < 2; h++) {
            const int rr = rbase + h * 8;
            if (rr >= M) continue;
#pragma unroll
            for (int na = 0; na < 4; na++) {
                const int cc = col0 + wn * 32 + na * 8 + (lane & 3) * 2;
                float vx = c[ma][na][h * 2 + 0];
                float vy = c[ma][na][h * 2 + 1];
                if (bias) { vx += bias[cc]; vy += bias[cc + 1]; }
                C[(size_t)rr * (P / 2) + (cc >> 1)] = __floats2half2_rn(vx, vy);
                ps[na][0] += vx; pq[na][0] += vx * vx;
                ps[na][1] += vy; pq[na][1] += vy * vy;
            }
        }
    }

    if (bn_layer >= 0) {
#pragma unroll
        for (int na = 0; na < 4; na++)
#pragma unroll
            for (int cq = 0; cq < 2; cq++) {
                float s = ps[na][cq], q = pq[na][cq];
#pragma unroll
                for (int o = 4; o < 32; o <<= 1) {
                    s += __shfl_xor_sync(0xffffffffu, s, o);
                    q += __shfl_xor_sync(0xffffffffu, q, o);
                }
                if ((lane >> 2) == 0) {
                    int col = col0 + wn * 32 + na * 8 + (lane & 3) * 2 + cq;
                    atomicAdd(&g_bnsum[bn_layer * HH + col], s);
                    atomicAdd(&g_bnsq[bn_layer * HH + col], q);
                }
            }
    }
}

// GAT GEMM: P=384, half2 out + fused attention dots
__global__ __launch_bounds__(256) void k_mma_gemm_gat(
    const __half* __restrict__ A, const float* __restrict__ W,
    const float* __restrict__ att_src, const float* __restrict__ att_dst,
    __half2* __restrict__ C, int M)
{
    const int P = HEADS * HH;
    extern __shared__ unsigned dsm[];
    const int t = threadIdx.x;
    const int lane = t & 31, warp = t >> 5;
    const int wr = warp & 3, wn = warp >> 2;
    const int row0 = blockIdx.y * 128, col0 = blockIdx.x * 64;
    const int head = col0 >> 7;
    const int jbase = col0 & 127;

    float c[2][4][4];
#pragma unroll
    for (int i = 0; i < 2; i++)
#pragma unroll
        for (int j = 0; j < 4; j++)
#pragma unroll
            for (int q = 0; q < 4; q++) c[i][j][q] = 0.f;

    uint4 pa[4];
    float2 pb[8];
    prefA_h(pa, A, row0, M, t, 0);
    prefB(pb, W, P, col0, t, 0);

    for (int ch = 0; ch < 2; ch++) {
        unsigned* As = dsm + (ch & 1) * CHUNK_UINTS;
        unsigned* Bs = As + 128 * A2PC;
        stsA_h(As, pa, t);
        stsB(Bs, pb, t);
        __syncthreads();
        if (ch == 0) {
            prefA_h(pa, A, row0, M, t, 1);
            prefB(pb, W, P, col0, t, 1);
        }
        mma_chunk(As, Bs, c, wr, wn, lane);
    }

    float asv[4][2], adv[4][2];
#pragma unroll
    for (int na = 0; na < 4; na++) {
        int j = jbase + wn * 32 + na * 8 + (lane & 3) * 2;
        asv[na][0] = att_src[head * HH + j];     asv[na][1] = att_src[head * HH + j + 1];
        adv[na][0] = att_dst[head * HH + j];     adv[na][1] = att_dst[head * HH + j + 1];
    }

#pragma unroll
    for (int ma = 0; ma < 2; ma++) {
        const int rbase = row0 + wr * 32 + ma * 16 + (lane >> 2);
#pragma unroll
        for (int h = 0; h < 2; h++) {
            const int rr = rbase + h * 8;
            float s1 = 0.f, s2 = 0.f;
#pragma unroll
            for (int na = 0; na < 4; na++) {
                float vx = c[ma][na][h * 2 + 0];
                float vy = c[ma][na][h * 2 + 1];
                s1 = fmaf(vx, asv[na][0], fmaf(vy, asv[na][1], s1));
                s2 = fmaf(vx, adv[na][0], fmaf(vy, adv[na][1], s2));
                if (rr < M) {
                    const int cc = col0 + wn * 32 + na * 8 + (lane & 3) * 2;
                    C[(size_t)rr * (P / 2) + (cc >> 1)] = __floats2half2_rn(vx, vy);
                }
            }
            s1 += __shfl_xor_sync(0xffffffffu, s1, 1);
            s1 += __shfl_xor_sync(0xffffffffu, s1, 2);
            s2 += __shfl_xor_sync(0xffffffffu, s2, 1);
            s2 += __shfl_xor_sync(0xffffffffu, s2, 2);
            if ((lane & 3) == 0 && rr < M) {
                atomicAdd(&g_asrc[rr * 3 + head], s1);
                atomicAdd(&g_adst[rr * 3 + head], s2);
            }
        }
    }
}

// ---------------- GCN gather: half in, half out (+ BN stats L0) ----------------
__global__ void k_gcn_gather(const __half2* __restrict__ t, const float* __restrict__ b1,
                             __half2* __restrict__ out) {
    __shared__ float sh_sum[HH], sh_sq[HH];
    const int tix = threadIdx.x;
    if (tix < HH) { sh_sum[tix] = 0.f; sh_sq[tix] = 0.f; }
    __syncthreads();
    const int lane = tix & 31;
    const int gwarp = (blockIdx.x * blockDim.x + tix) >> 5;
    const int nwarp = (gridDim.x * blockDim.x) >> 5;
    float4 b4 = ld4(b1 + lane * 4);
    float4 lsum = make_float4(0.f, 0.f, 0.f, 0.f), lsq = lsum;
    for (int n = gwarp; n < NN; n += nwarp) {
        float dn = g_dinv[n];
        float4 acc = f4scale(ldh4(t + (size_t)n * 64 + lane * 2), dn);
        int beg = g_rowptr[n], end = g_rowptr[n + 1];
        for (int idx = beg; idx < end; idx++) {
            int s = g_csr_src[idx];
            float ds = g_dinv[s];
            float4 v = ldh4(t + (size_t)s * 64 + lane * 2);
            acc.x = fmaf(v.x, ds, acc.x); acc.y = fmaf(v.y, ds, acc.y);
            acc.z = fmaf(v.z, ds, acc.z); acc.w = fmaf(v.w, ds, acc.w);
        }
        acc = f4scale(acc, dn);
        acc = f4add(acc, b4);
        sth4(out + (size_t)n * 64 + lane * 2, acc);
        lsum = f4add(lsum, acc);
        lsq.x = fmaf(acc.x, acc.x, lsq.x); lsq.y = fmaf(acc.y, acc.y, lsq.y);
        lsq.z = fmaf(acc.z, acc.z, lsq.z); lsq.w = fmaf(acc.w, acc.w, lsq.w);
    }
    atomicAdd(&sh_sum[lane * 4 + 0], lsum.x); atomicAdd(&sh_sq[lane * 4 + 0], lsq.x);
    atomicAdd(&sh_sum[lane * 4 + 1], lsum.y); atomicAdd(&sh_sq[lane * 4 + 1], lsq.y);
    atomicAdd(&sh_sum[lane * 4 + 2], lsum.z); atomicAdd(&sh_sq[lane * 4 + 2], lsq.z);
    atomicAdd(&sh_sum[lane * 4 + 3], lsum.w); atomicAdd(&sh_sq[lane * 4 + 3], lsq.w);
    __syncthreads();
    if (tix < HH) {
        atomicAdd(&g_bnsum[tix], sh_sum[tix]);
        atomicAdd(&g_bnsq[tix], sh_sq[tix]);
    }
}

// ---------------- SAGE mean gather: half in/out ----------------
__global__ void k_sage_gather(const __half2* __restrict__ h, __half2* __restrict__ out) {
    int wid = (blockIdx.x * blockDim.x + threadIdx.x) >> 5;
    int lane = threadIdx.x & 31;
    if (wid >= NN) return;
    int n = wid;
    float4 acc = make_float4(0.f, 0.f, 0.f, 0.f);
    int beg = g_rowptr[n], end = g_rowptr[n + 1];
    for (int idx = beg; idx < end; idx++) {
        int s = g_csr_src[idx];
        acc = f4add(acc, ldh4(h + (size_t)s * 64 + lane * 2));
    }
    float inv = 1.f / fmaxf((float)(end - beg), 1.f);
    sth4(out + (size_t)n * 64 + lane * 2, f4scale(acc, inv));
}

// ---------------- BN apply + ELU on half buffer ----------------
__global__ void k_bn_apply_elu_h(__half2* __restrict__ h, const float* __restrict__ gamma,
                                 const float* __restrict__ beta, int layer) {
    int i = blockIdx.x * blockDim.x + threadIdx.x;
    if (i >= NN * HH / 4) return;
    int j = (i * 4) & (HH - 1);
    const float invN = 1.f / (float)NN;
    float4 v = ldh4(h + (size_t)i * 2);
    float y[4] = {v.x, v.y, v.z, v.w};
#pragma unroll
    for (int q = 0; q < 4; q++) {
        float mean = g_bnsum[layer * HH + j + q] * invN;
        float var = fmaxf(g_bnsq[layer * HH + j + q] * invN - mean * mean, 0.f);
        float sc = gamma[j + q] * rsqrtf(var + EPS);
        float sh = beta[j + q] - mean * sc;
        y[q] = elu1(fmaf(y[q], sc, sh));
    }
    sth4(h + (size_t)i * 2, make_float4(y[0], y[1], y[2], y[3]));
}

// ---------------- GAT gather: inline softmax (__expf), half reads, fp32 out (+ BN stats L2) ----------------
__global__ void k_gat_gather(const float* __restrict__ b3, float* __restrict__ out) {
    __shared__ float sh_sum[HH], sh_sq[HH];
    const int tix = threadIdx.x;
    if (tix < HH) { sh_sum[tix] = 0.f; sh_sq[tix] = 0.f; }
    __syncthreads();
    const int lane = tix & 31;
    const int gwarp = (blockIdx.x * blockDim.x + tix) >> 5;
    const int nwarp = (gridDim.x * blockDim.x) >> 5;
    float4 b4 = ld4(b3 + lane * 4);
    float4 lsum = make_float4(0.f, 0.f, 0.f, 0.f), lsq = lsum;
    const __half2* h3 = g_h3;
    for (int n = gwarp; n < NN; n += nwarp) {
        float ad0 = g_adst[n * 3 + 0], ad1 = g_adst[n * 3 + 1], ad2 = g_adst[n * 3 + 2];
        float w0 = __expf(lrelu(g_asrc[n * 3 + 0] + ad0));
        float w1 = __expf(lrelu(g_asrc[n * 3 + 1] + ad1));
        float w2 = __expf(lrelu(g_asrc[n * 3 + 2] + ad2));
        float d0 = w0, d1 = w1, d2 = w2;
        const __half2* bp = h3 + (size_t)n * 192 + lane * 2;
        float2 p0 = __half22float2(bp[0]),   p1 = __half22float2(bp[1]);
        float2 q0 = __half22float2(bp[64]),  q1 = __half22float2(bp[65]);
        float2 r0 = __half22float2(bp[128]), r1 = __half22float2(bp[129]);
        float4 acc0 = make_float4(p0.x * w0, p0.y * w0, p1.x * w0, p1.y * w0);
        float4 acc1 = make_float4(q0.x * w1, q0.y * w1, q1.x * w1, q1.y * w1);
        float4 acc2 = make_float4(r0.x * w2, r0.y * w2, r1.x * w2, r1.y * w2);
        int beg = g_rowptr[n], end = g_rowptr[n + 1];
        for (int idx = beg; idx < end; idx++) {
            int s = g_csr_src[idx];
            float e0 = __expf(lrelu(g_asrc[s * 3 + 0] + ad0));
            float e1 = __expf(lrelu(g_asrc[s * 3 + 1] + ad1));
            float e2 = __expf(lrelu(g_asrc[s * 3 + 2] + ad2));
            d0 += e0; d1 += e1; d2 += e2;
            const __half2* sp = h3 + (size_t)s * 192 + lane * 2;
            float2 a0 = __half22float2(sp[0]),   a1 = __half22float2(sp[1]);
            float2 b0 = __half22float2(sp[64]),  b1_ = __half22float2(sp[65]);
            float2 c0 = __half22float2(sp[128]), c1 = __half22float2(sp[129]);
            acc0.x = fmaf(a0.x, e0, acc0.x); acc0.y = fmaf(a0.y, e0, acc0.y);
            acc0.z = fmaf(a1.x, e0, acc0.z); acc0.w = fmaf(a1.y, e0, acc0.w);
            acc1.x = fmaf(b0.x, e1, acc1.x); acc1.y = fmaf(b0.y, e1, acc1.y);
            acc1.z = fmaf(b1_.x, e1, acc1.z); acc1.w = fmaf(b1_.y, e1, acc1.w);
            acc2.x = fmaf(c0.x, e2, acc2.x); acc2.y = fmaf(c0.y, e2, acc2.y);
            acc2.z = fmaf(c1.x, e2, acc2.z); acc2.w = fmaf(c1.y, e2, acc2.w);
        }
        float i0 = 1.f / d0, i1 = 1.f / d1, i2 = 1.f / d2;
        float4 r;
        r.x = (acc0.x * i0 + acc1.x * i1 + acc2.x * i2) * (1.f / 3.f) + b4.x;
        r.y = (acc0.y * i0 + acc1.y * i1 + acc2.y * i2) * (1.f / 3.f) + b4.y;
        r.z = (acc0.z * i0 + acc1.z * i1 + acc2.z * i2) * (1.f / 3.f) + b4.z;
        r.w = (acc0.w * i0 + acc1.w * i1 + acc2.w * i2) * (1.f / 3.f) + b4.w;
        st4(out + (size_t)n * HH + lane * 4, r);
        lsum = f4add(lsum, r);
        lsq.x = fmaf(r.x, r.x, lsq.x); lsq.y = fmaf(r.y, r.y, lsq.y);
        lsq.z = fmaf(r.z, r.z, lsq.z); lsq.w = fmaf(r.w, r.w, lsq.w);
    }
    atomicAdd(&sh_sum[lane * 4 + 0], lsum.x); atomicAdd(&sh_sq[lane * 4 + 0], lsq.x);
    atomicAdd(&sh_sum[lane * 4 + 1], lsum.y); atomicAdd(&sh_sq[lane * 4 + 1], lsq.y);
    atomicAdd(&sh_sum[lane * 4 + 2], lsum.z); atomicAdd(&sh_sq[lane * 4 + 2], lsq.z);
    atomicAdd(&sh_sum[lane * 4 + 3], lsum.w); atomicAdd(&sh_sq[lane * 4 + 3], lsq.w);
    __syncthreads();
    if (tix < HH) {
        atomicAdd(&g_bnsum[2 * HH + tix], sh_sum[tix]);
        atomicAdd(&g_bnsq[2 * HH + tix], sh_sq[tix]);
    }
}

// ---------------- pooling with fused BN apply + ELU (layer 2) ----------------
__global__ void k_pool_bn(const float* __restrict__ h, const float* __restrict__ gamma,
                          const float* __restrict__ beta) {
    int gw = (blockIdx.x * blockDim.x + threadIdx.x) >> 5;
    int lane = threadIdx.x & 31;
    int n0 = gw * 8;
    if (n0 >= NN) return;
    const float invN = 1.f / (float)NN;
    float4 sc, sh;
    {
        int j = lane * 4;
        float m0 = g_bnsum[2 * HH + j + 0] * invN, m1 = g_bnsum[2 * HH + j + 1] * invN;
        float m2 = g_bnsum[2 * HH + j + 2] * invN, m3 = g_bnsum[2 * HH + j + 3] * invN;
        float v0 = fmaxf(g_bnsq[2 * HH + j + 0] * invN - m0 * m0, 0.f);
        float v1 = fmaxf(g_bnsq[2 * HH + j + 1] * invN - m1 * m1, 0.f);
        float v2 = fmaxf(g_bnsq[2 * HH + j + 2] * invN - m2 * m2, 0.f);
        float v3 = fmaxf(g_bnsq[2 * HH + j + 3] * invN - m3 * m3, 0.f);
        sc.x = gamma[j + 0] * rsqrtf(v0 + EPS); sh.x = beta[j + 0] - m0 * sc.x;
        sc.y = gamma[j + 1] * rsqrtf(v1 + EPS); sh.y = beta[j + 1] - m1 * sc.y;
        sc.z = gamma[j + 2] * rsqrtf(v2 + EPS); sh.z = beta[j + 2] - m2 * sc.z;
        sc.w = gamma[j + 3] * rsqrtf(v3 + EPS); sh.w = beta[j + 3] - m3 * sc.w;
    }
    float4 acc = make_float4(0.f, 0.f, 0.f, 0.f);
    int cur = g_batch[n0];
    float cnt = 0.f;
    for (int j = 0; j < 8; j++) {
        int n = n0 + j;
        if (n >= NN) break;
        int b = g_batch[n];
        float4 v = ld4(h + (size_t)n * HH + lane * 4);
        float y0 = elu1(fmaf(v.x, sc.x, sh.x));
        float y1 = elu1(fmaf(v.y, sc.y, sh.y));
        float y2 = elu1(fmaf(v.z, sc.z, sh.z));
        float y3 = elu1(fmaf(v.w, sc.w, sh.w));
        if (b != cur) {
            float* p = g_pool + (size_t)cur * HH + lane * 4;
            atomicAdd(p + 0, acc.x); atomicAdd(p + 1, acc.y);
            atomicAdd(p + 2, acc.z); atomicAdd(p + 3, acc.w);
            if (lane == 0) atomicAdd(&g_cnt[cur], cnt);
            acc = make_float4(0.f, 0.f, 0.f, 0.f);
            cnt = 0.f;
            cur = b;
        }
        acc.x += y0; acc.y += y1; acc.z += y2; acc.w += y3;
        cnt += 1.f;
    }
    float* p = g_pool + (size_t)cur * HH + lane * 4;
    atomicAdd(p + 0, acc.x); atomicAdd(p + 1, acc.y);
    atomicAdd(p + 2, acc.z); atomicAdd(p + 3, acc.w);
    if (lane == 0) atomicAdd(&g_cnt[cur], cnt);
}

// ---------------- final: normalize pool + classifier ----------------
__global__ void k_pool_fin_cls(const float* __restrict__ Wc, const float* __restrict__ bc,
                               float* __restrict__ outp, float* __restrict__ outl) {
    __shared__ float sm[HH];
    int g = blockIdx.x;
    int t = threadIdx.x;
    float c = g_cnt[g];
    float v = g_pool[g * HH + t] / fmaxf(c, 1.f);
    if (outp) outp[g * HH + t] = v;
    sm[t] = v;
    __syncthreads();
    if (t < CC) {
        float s = bc[t];
        for (int k = 0; k < HH; k++) s = fmaf(sm[k], Wc[k * CC + t], s);
        if (outl) outl[g * CC + t] = s;
    }
}

// ---------------- host ----------------
extern "C" void kernel_launch(void* const* d_in, const int* in_sizes, int n_in,
                              void* d_out, int out_size) {
    const float* x        = (const float*)d_in[0];
    const void*  edge     = d_in[1];
    const void*  batch    = d_in[2];
    const float* W1       = (const float*)d_in[3];
    const float* b1       = (const float*)d_in[4];
    const float* gamma1   = (const float*)d_in[5];
    const float* beta1    = (const float*)d_in[6];
    const float* Wl       = (const float*)d_in[7];
    const float* bl       = (const float*)d_in[8];
    const float* Wr       = (const float*)d_in[9];
    const float* gamma2   = (const float*)d_in[10];
    const float* beta2    = (const float*)d_in[11];
    const float* W3       = (const float*)d_in[12];
    const float* att_src  = (const float*)d_in[13];
    const float* att_dst  = (const float*)d_in[14];
    const float* b3       = (const float*)d_in[15];
    const float* gamma3   = (const float*)d_in[16];
    const float* beta3    = (const float*)d_in[17];
    const float* Wc       = (const float*)d_in[18];
    const float* bc       = (const float*)d_in[19];

    float* out = (float*)d_out;
    float* out_pool = nullptr;
    float* out_log = nullptr;
    if (out_size >= GG * HH + GG * CC) { out_pool = out; out_log = out + GG * HH; }
    else if (out_size == GG * CC) { out_log = out; }
    else { out_pool = out; }

    __half *hx, *ha, *hb, *hc;
    __half2* h3;
    float* gout;
    cudaGetSymbolAddress((void**)&hx, g_hx);
    cudaGetSymbolAddress((void**)&ha, g_ha);
    cudaGetSymbolAddress((void**)&hb, g_hb);
    cudaGetSymbolAddress((void**)&hc, g_hc);
    cudaGetSymbolAddress((void**)&h3, g_h3);
    cudaGetSymbolAddress((void**)&gout, g_gout);

    static int smem_set = 0;
    if (!smem_set) {
        cudaFuncSetAttribute(k_mma_gemm, cudaFuncAttributeMaxDynamicSharedMemorySize, GEMM_SMEM_P);
        cudaFuncSetAttribute(k_mma_gemm_gat, cudaFuncAttributeMaxDynamicSharedMemorySize, GEMM_SMEM_P);
        smem_set = 1;
    }

    const int EB = (EE + 255) / 256;
    const int NB = (NN + 255) / 256;
    const int IB = (3 * NN + 255) / 256;
    const int WB = (NN * 32 + 255) / 256;
    const int SB = 592;
    const int AB = (NN * HH / 4 + 255) / 256;
    const int MB = (NN + 127) / 128;
    const int PB = ((NN + 7) / 8 * 32 + 255) / 256;

    // graph preprocessing (+ x fp16 conversion)
    k_init<<<IB, 256>>>(batch, edge);
    k_x2h<<<AB, 256>>>(x, (__half2*)hx);
    k_count<<<EB, 256>>>(edge);
    k_scan_part<<<NB, 256>>>();
    k_scan_mid<<<1, 256>>>(NB);
    k_scan_out<<<NB, 256>>>();
    k_fill_csr<<<EB, 256>>>(edge);

    // Layer 1: GCN
    k_mma_gemm<<<dim3(HH / 64, MB), 256, GEMM_SMEM_P>>>(hx, W1, nullptr, nullptr, nullptr,
                                                        (__half2*)ha, NN, HH, -1);
    k_gcn_gather<<<SB, 256>>>((__half2*)ha, b1, (__half2*)hb);
    k_bn_apply_elu_h<<<AB, 256>>>((__half2*)hb, gamma1, beta1, 0);

    // Layer 2: SAGE (dual-A pipelined GEMM + stats)
    k_sage_gather<<<WB, 256>>>((__half2*)hb, (__half2*)ha);
    k_mma_gemm<<<dim3(HH / 64, MB), 256, GEMM_SMEM_P>>>(ha, Wl, hb, Wr, bl,
                                                        (__half2*)hc, NN, HH, 1);
    k_bn_apply_elu_h<<<AB, 256>>>((__half2*)hc, gamma2, beta2, 1);

    // Layer 3: GAT
    k_mma_gemm_gat<<<dim3(HEADS * HH / 64, MB), 256, GEMM_SMEM_P>>>(hc, W3, att_src, att_dst, h3, NN);
    k_gat_gather<<<SB, 256>>>(b3, gout);

    // pooling (fused BN apply L2 + ELU) + classifier
    k_pool_bn<<<PB, 256>>>(gout, gamma3, beta3);
    k_pool_fin_cls<<<GG, HH>>>(Wc, bc, out_pool, out_log);
}